// round 8
// baseline (speedup 1.0000x reference)
#include <cuda_runtime.h>
#include <cuda_fp16.h>
#include <math.h>
#include <stdint.h>

// Problem constants
#define BB   128
#define TT   256
#define CC   384
#define HH   6
#define DD   64
#define NROWS (BB*TT)          // 32768
#define QKVW  (3*CC)           // 1152
#define FFN   (4*CC)           // 1536
#define LN_EPS 1e-5f
#define ATT_SCALE 0.05103103630798287f   // 384^-0.5

typedef __half half_t;

// ---------------------------------------------------------------------------
// Scratch (device globals; allocation is forbidden)
// ---------------------------------------------------------------------------
__device__ half_t g_xn  [(size_t)NROWS*CC];
__device__ half_t g_qkv [(size_t)NROWS*QKVW];
__device__ half_t g_o   [(size_t)NROWS*CC];
__device__ float  g_x1  [(size_t)NROWS*CC];
__device__ half_t g_xn2 [(size_t)NROWS*CC];
__device__ half_t g_h   [(size_t)NROWS*FFN];
// packed weights, [N, K] K-major fp16
__device__ half_t g_wqkv[(size_t)QKVW*CC];
__device__ half_t g_wo  [(size_t)CC*CC];
__device__ half_t g_w1  [(size_t)FFN*CC];
__device__ half_t g_w2  [(size_t)CC*FFN];

// ---------------------------------------------------------------------------
// Helpers
// ---------------------------------------------------------------------------
__device__ __forceinline__ uint32_t smem_u32(const void* p) {
    return (uint32_t)__cvta_generic_to_shared(p);
}

#define CP_ASYNC16(dst, src) \
    asm volatile("cp.async.cg.shared.global [%0], [%1], 16;" :: "r"(dst), "l"(src))
#define CP_COMMIT() asm volatile("cp.async.commit_group;" ::: "memory")
#define CP_WAIT(n)  asm volatile("cp.async.wait_group %0;" :: "n"(n) : "memory")

#define LDSM_X4(r0, r1, r2, r3, addr) \
    asm volatile("ldmatrix.sync.aligned.m8n8.x4.shared.b16 {%0,%1,%2,%3}, [%4];" \
        : "=r"(r0), "=r"(r1), "=r"(r2), "=r"(r3) : "r"(addr))

#define LDSM_X4_T(r0, r1, r2, r3, addr) \
    asm volatile("ldmatrix.sync.aligned.m8n8.x4.trans.shared.b16 {%0,%1,%2,%3}, [%4];" \
        : "=r"(r0), "=r"(r1), "=r"(r2), "=r"(r3) : "r"(addr))

// fp32-accumulator MMA (used by attention)
#define MMA_F16(d0, d1, d2, d3, a0, a1, a2, a3, b0, b1) \
    asm volatile("mma.sync.aligned.m16n8k16.row.col.f32.f16.f16.f32 " \
        "{%0,%1,%2,%3}, {%4,%5,%6,%7}, {%8,%9}, {%0,%1,%2,%3};" \
        : "+f"(d0), "+f"(d1), "+f"(d2), "+f"(d3) \
        : "r"(a0), "r"(a1), "r"(a2), "r"(a3), "r"(b0), "r"(b1))

// fp16-accumulator MMA, in-place chain
#define MMA_H(d0, d1, a0, a1, a2, a3, b0, b1) \
    asm volatile("mma.sync.aligned.m16n8k16.row.col.f16.f16.f16.f16 " \
        "{%0,%1}, {%2,%3,%4,%5}, {%6,%7}, {%0,%1};" \
        : "+r"(d0), "+r"(d1) \
        : "r"(a0), "r"(a1), "r"(a2), "r"(a3), "r"(b0), "r"(b1))

// fp16-accumulator MMA, chain start (c = zero)
#define MMA_H_INIT(d0, d1, a0, a1, a2, a3, b0, b1, z) \
    asm volatile("mma.sync.aligned.m16n8k16.row.col.f16.f16.f16.f16 " \
        "{%0,%1}, {%2,%3,%4,%5}, {%6,%7}, {%8,%8};" \
        : "=r"(d0), "=r"(d1) \
        : "r"(a0), "r"(a1), "r"(a2), "r"(a3), "r"(b0), "r"(b1), "r"(z))

__device__ __forceinline__ uint32_t pack_h2(float a, float b) {
    __half2 h = __floats2half2_rn(a, b);
    return *(uint32_t*)&h;
}

// ---------------------------------------------------------------------------
// Combined weight prep (one launch for all four weight tensors)
// ---------------------------------------------------------------------------
#define NW_QKV (QKVW*CC)
#define NW_O   (CC*CC)
#define NW_1   (FFN*CC)
#define NW_2   (CC*FFN)
#define NW_TOT (NW_QKV+NW_O+NW_1+NW_2)

__global__ void pack_all_kernel(const float* __restrict__ Wq,
                                const float* __restrict__ Wk,
                                const float* __restrict__ Wv,
                                const float* __restrict__ Wo,
                                const float* __restrict__ W1,
                                const float* __restrict__ W2,
                                half_t* __restrict__ wqkv,
                                half_t* __restrict__ wo,
                                half_t* __restrict__ w1,
                                half_t* __restrict__ w2)
{
    int idx = blockIdx.x * 256 + threadIdx.x;
    if (idx < NW_QKV) {
        int n = idx / CC, k = idx % CC;
        int proj = n / CC, hd = n % CC;
        int h = hd >> 6, d = hd & 63;
        const float* W = (proj == 0) ? Wq : ((proj == 1) ? Wk : Wv);
        wqkv[idx] = __float2half(W[(size_t)(h * CC + k) * DD + d]);
        return;
    }
    idx -= NW_QKV;
    if (idx < NW_O) {
        int n = idx / CC, k = idx % CC;
        wo[idx] = __float2half(Wo[(size_t)k * CC + n]);
        return;
    }
    idx -= NW_O;
    if (idx < NW_1) {
        int n = idx / CC, k = idx % CC;
        w1[idx] = __float2half(W1[(size_t)k * FFN + n]);
        return;
    }
    idx -= NW_1;
    if (idx < NW_2) {
        int n = idx / FFN, k = idx % FFN;
        w2[idx] = __float2half(W2[(size_t)k * CC + n]);
    }
}

// ---------------------------------------------------------------------------
// LayerNorm with fp16 output
// ---------------------------------------------------------------------------
__global__ void __launch_bounds__(128) ln_kernel(const float* __restrict__ x,
                                                 const float* __restrict__ g,
                                                 const float* __restrict__ be,
                                                 half_t* __restrict__ out)
{
    const int row = blockIdx.x;
    const int tid = threadIdx.x;
    const float* xr = x + (size_t)row * CC;

    float v0 = xr[tid], v1 = xr[tid + 128], v2 = xr[tid + 256];
    float s  = v0 + v1 + v2;
    float sq = v0*v0 + v1*v1 + v2*v2;

    #pragma unroll
    for (int off = 16; off > 0; off >>= 1) {
        s  += __shfl_xor_sync(0xffffffffu, s,  off);
        sq += __shfl_xor_sync(0xffffffffu, sq, off);
    }
    __shared__ float ss[4], ssq[4];
    const int wid = tid >> 5, lane = tid & 31;
    if (lane == 0) { ss[wid] = s; ssq[wid] = sq; }
    __syncthreads();
    s  = ss[0]  + ss[1]  + ss[2]  + ss[3];
    sq = ssq[0] + ssq[1] + ssq[2] + ssq[3];

    const float mu  = s * (1.0f / CC);
    const float var = sq * (1.0f / CC) - mu * mu;
    const float inv = rsqrtf(var + LN_EPS);

    size_t rb = (size_t)row * CC;
    out[rb + tid      ] = __float2half((v0 - mu) * inv * g[tid      ] + be[tid      ]);
    out[rb + tid + 128] = __float2half((v1 - mu) * inv * g[tid + 128] + be[tid + 128]);
    out[rb + tid + 256] = __float2half((v2 - mu) * inv * g[tid + 256] + be[tid + 256]);
}

// ---------------------------------------------------------------------------
// fp16 HMMA GEMM, 3-stage cp.async pipeline, CHUNKED FP16 ACCUMULATION.
// CTA tile 128x128, 4 warps (2x2), warp tile 64x64, K-chunks of 64.
// Within a chunk the 4 k-step MMAs chain in fp16 accumulators (testing the
// 2x-rate fp16-acc path); promoted into fp32 master accs once per chunk.
//   EPI 0: fp16 out   EPI 1: +bias+res -> f32   EPI 2: relu(+bias) -> fp16
// ---------------------------------------------------------------------------
#define RPAD 144
#define T_A  0
#define T_B  (128*RPAD)
#define BUFSZ (2*128*RPAD)            // 36864 per stage
#define NSTAGE 3
#define SMG_TOTAL (NSTAGE*BUFSZ)      // 110592

__device__ __forceinline__ void prefetch_chunk(
    uint32_t sbuf, const half_t* __restrict__ A, const half_t* __restrict__ B,
    int row0, int col0, int K, int k0, int tid)
{
    #pragma unroll
    for (int i = 0; i < 16; i++) {
        int idx = tid + i * 128;
        int r = idx >> 3, cp = idx & 7;
        if (r < 128) {
            CP_ASYNC16(sbuf + T_A + (uint32_t)(r * RPAD + cp * 16),
                       A + (size_t)(row0 + r) * K + k0 + cp * 8);
        } else {
            int rr = r - 128;
            CP_ASYNC16(sbuf + T_B + (uint32_t)(rr * RPAD + cp * 16),
                       B + (size_t)(col0 + rr) * K + k0 + cp * 8);
        }
    }
}

template <int EPI>
__global__ void __launch_bounds__(128)
mma_gemm_kernel(const half_t* __restrict__ A, const half_t* __restrict__ B,
                float* __restrict__ Cf, half_t* __restrict__ Ch,
                int K, int M,
                const float* __restrict__ bias, const float* __restrict__ res)
{
    extern __shared__ char sm[];
    const uint32_t sbase = smem_u32(sm);
    const int tid  = threadIdx.x;
    const int warp = tid >> 5, lane = tid & 31;
    const int wrow = warp >> 1, wcol = warp & 1;   // 2 x 2 warp grid, 64x64 tiles
    const int row0 = blockIdx.y * 128;
    const int col0 = blockIdx.x * 128;

    const int quad = lane >> 3, il = lane & 7;
    const uint32_t aoff = (uint32_t)((wrow * 64 + (quad & 1) * 8 + il) * RPAD
                                     + (quad >> 1) * 16);
    const uint32_t boff = (uint32_t)((wcol * 64 + (quad >> 1) * 8 + il) * RPAD
                                     + (quad & 1) * 16);

    float acc[4][8][4];
    #pragma unroll
    for (int m = 0; m < 4; m++)
        #pragma unroll
        for (int n = 0; n < 8; n++)
            #pragma unroll
            for (int k = 0; k < 4; k++) acc[m][n][k] = 0.0f;

    const uint32_t zz = 0;
    const int nch = K >> 6;

    prefetch_chunk(sbase, A, B, row0, col0, K, 0, tid);
    CP_COMMIT();
    prefetch_chunk(sbase + BUFSZ, A, B, row0, col0, K, 64, tid);
    CP_COMMIT();

    int sread = 0, swrite = 2;
    for (int ch = 0; ch < nch; ch++) {
        if (ch + 1 < nch) { CP_WAIT(1); } else { CP_WAIT(0); }
        __syncthreads();

        if (ch + 2 < nch) {
            prefetch_chunk(sbase + swrite * BUFSZ, A, B,
                           row0, col0, K, (ch + 2) << 6, tid);
            CP_COMMIT();
            swrite = (swrite + 1 == NSTAGE) ? 0 : swrite + 1;
        }

        const uint32_t sbuf = sbase + sread * BUFSZ;
        sread = (sread + 1 == NSTAGE) ? 0 : sread + 1;

        uint32_t hacc[4][8][2];     // fp16 chunk accumulators

        #pragma unroll
        for (int ks = 0; ks < 4; ks++) {
            const uint32_t ksb = ks * 32;
            uint32_t b[16];
            #pragma unroll
            for (int np = 0; np < 4; np++)
                LDSM_X4(b[np*4], b[np*4+1], b[np*4+2], b[np*4+3],
                        sbuf + T_B + boff + np * 16 * RPAD + ksb);

            #pragma unroll
            for (int mt = 0; mt < 4; mt++) {
                uint32_t a[4];
                LDSM_X4(a[0], a[1], a[2], a[3],
                        sbuf + T_A + aoff + mt * 16 * RPAD + ksb);
                #pragma unroll
                for (int nt = 0; nt < 8; nt++) {
                    if (ks == 0) {
                        MMA_H_INIT(hacc[mt][nt][0], hacc[mt][nt][1],
                                   a[0], a[1], a[2], a[3],
                                   b[nt*2], b[nt*2+1], zz);
                    } else {
                        MMA_H(hacc[mt][nt][0], hacc[mt][nt][1],
                              a[0], a[1], a[2], a[3],
                              b[nt*2], b[nt*2+1]);
                    }
                }
            }
        }

        // promote fp16 chunk sums into fp32 master accumulators
        #pragma unroll
        for (int mt = 0; mt < 4; mt++)
            #pragma unroll
            for (int nt = 0; nt < 8; nt++) {
                float2 p0 = __half22float2(*(__half2*)&hacc[mt][nt][0]);
                float2 p1 = __half22float2(*(__half2*)&hacc[mt][nt][1]);
                acc[mt][nt][0] += p0.x;
                acc[mt][nt][1] += p0.y;
                acc[mt][nt][2] += p1.x;
                acc[mt][nt][3] += p1.y;
            }
    }

    const int r_l = lane >> 2;
    const int c_l = (lane & 3) << 1;
    #pragma unroll
    for (int mt = 0; mt < 4; mt++) {
        #pragma unroll
        for (int nt = 0; nt < 8; nt++) {
            const int r = row0 + wrow * 64 + mt * 16 + r_l;
            const int c = col0 + wcol * 64 + nt * 8 + c_l;
            const float* d = acc[mt][nt];
            #pragma unroll
            for (int half_i = 0; half_i < 2; half_i++) {
                const int rr = r + half_i * 8;
                const size_t off = (size_t)rr * M + c;
                float v0 = d[half_i * 2], v1 = d[half_i * 2 + 1];
                if (EPI == 0) {
                    *(__half2*)&Ch[off] = __floats2half2_rn(v0, v1);
                } else if (EPI == 1) {
                    float2 rv = *(const float2*)&res[off];
                    *(float2*)&Cf[off] = make_float2(v0 + bias[c] + rv.x,
                                                     v1 + bias[c + 1] + rv.y);
                } else {
                    v0 = fmaxf(v0 + bias[c],     0.0f);
                    v1 = fmaxf(v1 + bias[c + 1], 0.0f);
                    *(__half2*)&Ch[off] = __floats2half2_rn(v0, v1);
                }
            }
        }
    }
}

// ---------------------------------------------------------------------------
// Tensor-core causal flash attention with double-buffered K/V (unchanged).
// ---------------------------------------------------------------------------
#define ARPAD 144
__global__ void __launch_bounds__(128) attn_kernel(const half_t* __restrict__ qkv,
                                                   half_t* __restrict__ o)
{
    __shared__ char smem[5 * 64 * ARPAD];
    const uint32_t sb  = smem_u32(smem);
    const uint32_t KV0 = sb + 64 * ARPAD;

    const int qt = blockIdx.x;
    const int h  = blockIdx.y;
    const int b  = blockIdx.z;
    const int tid  = threadIdx.x;
    const int warp = tid >> 5, lane = tid & 31;
    const int quad = lane >> 3, il = lane & 7;
    const int r_l  = lane >> 2, c_l = (lane & 3) << 1;

    const size_t qrow0 = (size_t)(b * TT + qt * 64);
    const half_t* qg = qkv + qrow0 * QKVW + h * 64;
    const half_t* kvg = qkv + (size_t)(b * TT) * QKVW + CC + h * 64;

    #pragma unroll
    for (int i = 0; i < 4; i++) {
        int idx = tid + i * 128;
        int r = idx >> 3, cp = idx & 7;
        CP_ASYNC16(sb + (uint32_t)(r * ARPAD + cp * 16),
                   qg + (size_t)r * QKVW + cp * 8);
    }
    CP_COMMIT();

    #pragma unroll
    for (int i = 0; i < 4; i++) {
        int idx = tid + i * 128;
        int r = idx >> 3, cp = idx & 7;
        const half_t* kg = kvg + (size_t)r * QKVW + cp * 8;
        CP_ASYNC16(KV0 + (uint32_t)(r * ARPAD + cp * 16), kg);
        CP_ASYNC16(KV0 + (uint32_t)((64 + r) * ARPAD + cp * 16), kg + CC);
    }
    CP_COMMIT();

    CP_WAIT(1);
    __syncthreads();

    uint32_t qa[4][4];
    {
        const uint32_t aoff = sb + (uint32_t)((warp * 16 + (quad & 1) * 8 + il) * ARPAD
                                              + (quad >> 1) * 16);
        #pragma unroll
        for (int ks = 0; ks < 4; ks++)
            LDSM_X4(qa[ks][0], qa[ks][1], qa[ks][2], qa[ks][3], aoff + ks * 32);
    }

    float m0 = -1e30f, m1 = -1e30f, l0 = 0.0f, l1 = 0.0f;
    float oacc[8][4];
    #pragma unroll
    for (int nt = 0; nt < 8; nt++)
        #pragma unroll
        for (int j = 0; j < 4; j++) oacc[nt][j] = 0.0f;

    const uint32_t klane = (uint32_t)(((quad >> 1) * 8 + il) * ARPAD + (quad & 1) * 16);
    const uint32_t vlane = (uint32_t)(((quad & 1) * 8 + il) * ARPAD + (quad >> 1) * 16);

    const int lrow0 = warp * 16 + r_l;
    const int lrow1 = lrow0 + 8;

    for (int jt = 0; jt <= qt; jt++) {
        CP_WAIT(0);
        __syncthreads();

        if (jt < qt) {
            const uint32_t kvn = KV0 + ((jt + 1) & 1) * 2 * 64 * ARPAD;
            const half_t* kg0 = kvg + (size_t)((jt + 1) * 64) * QKVW;
            #pragma unroll
            for (int i = 0; i < 4; i++) {
                int idx = tid + i * 128;
                int r = idx >> 3, cp = idx & 7;
                const half_t* kg = kg0 + (size_t)r * QKVW + cp * 8;
                CP_ASYNC16(kvn + (uint32_t)(r * ARPAD + cp * 16), kg);
                CP_ASYNC16(kvn + (uint32_t)((64 + r) * ARPAD + cp * 16), kg + CC);
            }
            CP_COMMIT();
        }

        const uint32_t kvs = KV0 + (jt & 1) * 2 * 64 * ARPAD;
        const uint32_t koff = kvs + klane;
        const uint32_t voff = kvs + 64 * ARPAD + vlane;

        float s[8][4];
        #pragma unroll
        for (int nt = 0; nt < 8; nt++)
            #pragma unroll
            for (int j = 0; j < 4; j++) s[nt][j] = 0.0f;

        #pragma unroll
        for (int np = 0; np < 4; np++) {
            #pragma unroll
            for (int ks = 0; ks < 4; ks++) {
                uint32_t bb[4];
                LDSM_X4(bb[0], bb[1], bb[2], bb[3],
                        koff + np * 16 * ARPAD + ks * 32);
                MMA_F16(s[2*np][0],   s[2*np][1],   s[2*np][2],   s[2*np][3],
                        qa[ks][0], qa[ks][1], qa[ks][2], qa[ks][3], bb[0], bb[1]);
                MMA_F16(s[2*np+1][0], s[2*np+1][1], s[2*np+1][2], s[2*np+1][3],
                        qa[ks][0], qa[ks][1], qa[ks][2], qa[ks][3], bb[2], bb[3]);
            }
        }

        if (jt == qt) {
            #pragma unroll
            for (int nt = 0; nt < 8; nt++) {
                int col0c = nt * 8 + c_l;
                s[nt][0] = (col0c     > lrow0) ? -1e30f : s[nt][0] * ATT_SCALE;
                s[nt][1] = (col0c + 1 > lrow0) ? -1e30f : s[nt][1] * ATT_SCALE;
                s[nt][2] = (col0c     > lrow1) ? -1e30f : s[nt][2] * ATT_SCALE;
                s[nt][3] = (col0c + 1 > lrow1) ? -1e30f : s[nt][3] * ATT_SCALE;
            }
        } else {
            #pragma unroll
            for (int nt = 0; nt < 8; nt++)
                #pragma unroll
                for (int j = 0; j < 4; j++) s[nt][j] *= ATT_SCALE;
        }

        float mx0 = -1e30f, mx1 = -1e30f;
        #pragma unroll
        for (int nt = 0; nt < 8; nt++) {
            mx0 = fmaxf(mx0, fmaxf(s[nt][0], s[nt][1]));
            mx1 = fmaxf(mx1, fmaxf(s[nt][2], s[nt][3]));
        }
        mx0 = fmaxf(mx0, __shfl_xor_sync(0xffffffffu, mx0, 1));
        mx0 = fmaxf(mx0, __shfl_xor_sync(0xffffffffu, mx0, 2));
        mx1 = fmaxf(mx1, __shfl_xor_sync(0xffffffffu, mx1, 1));
        mx1 = fmaxf(mx1, __shfl_xor_sync(0xffffffffu, mx1, 2));

        const float nm0 = fmaxf(m0, mx0), nm1 = fmaxf(m1, mx1);
        const float fac0 = __expf(m0 - nm0), fac1 = __expf(m1 - nm1);
        m0 = nm0; m1 = nm1;

        float ps0 = 0.0f, ps1 = 0.0f;
        #pragma unroll
        for (int nt = 0; nt < 8; nt++) {
            s[nt][0] = __expf(s[nt][0] - nm0);
            s[nt][1] = __expf(s[nt][1] - nm0);
            s[nt][2] = __expf(s[nt][2] - nm1);
            s[nt][3] = __expf(s[nt][3] - nm1);
            ps0 += s[nt][0] + s[nt][1];
            ps1 += s[nt][2] + s[nt][3];
        }
        ps0 += __shfl_xor_sync(0xffffffffu, ps0, 1);
        ps0 += __shfl_xor_sync(0xffffffffu, ps0, 2);
        ps1 += __shfl_xor_sync(0xffffffffu, ps1, 1);
        ps1 += __shfl_xor_sync(0xffffffffu, ps1, 2);
        l0 = l0 * fac0 + ps0;
        l1 = l1 * fac1 + ps1;

        #pragma unroll
        for (int nt = 0; nt < 8; nt++) {
            oacc[nt][0] *= fac0; oacc[nt][1] *= fac0;
            oacc[nt][2] *= fac1; oacc[nt][3] *= fac1;
        }

        #pragma unroll
        for (int ks = 0; ks < 4; ks++) {
            uint32_t pa[4];
            pa[0] = pack_h2(s[2*ks][0],   s[2*ks][1]);
            pa[1] = pack_h2(s[2*ks][2],   s[2*ks][3]);
            pa[2] = pack_h2(s[2*ks+1][0], s[2*ks+1][1]);
            pa[3] = pack_h2(s[2*ks+1][2], s[2*ks+1][3]);
            #pragma unroll
            for (int np = 0; np < 4; np++) {
                uint32_t vb[4];
                LDSM_X4_T(vb[0], vb[1], vb[2], vb[3],
                          voff + ks * 16 * ARPAD + np * 32);
                MMA_F16(oacc[2*np][0],   oacc[2*np][1],   oacc[2*np][2],   oacc[2*np][3],
                        pa[0], pa[1], pa[2], pa[3], vb[0], vb[1]);
                MMA_F16(oacc[2*np+1][0], oacc[2*np+1][1], oacc[2*np+1][2], oacc[2*np+1][3],
                        pa[0], pa[1], pa[2], pa[3], vb[2], vb[3]);
            }
        }
    }

    const float inv0 = 1.0f / l0, inv1 = 1.0f / l1;
    half_t* og = o + (qrow0 + warp * 16) * CC + h * 64;
    #pragma unroll
    for (int nt = 0; nt < 8; nt++) {
        const int col = nt * 8 + c_l;
        *(__half2*)&og[(size_t)r_l * CC + col] =
            __floats2half2_rn(oacc[nt][0] * inv0, oacc[nt][1] * inv0);
        *(__half2*)&og[(size_t)(r_l + 8) * CC + col] =
            __floats2half2_rn(oacc[nt][2] * inv1, oacc[nt][3] * inv1);
    }
}

// ---------------------------------------------------------------------------
// Launch
// ---------------------------------------------------------------------------
extern "C" void kernel_launch(void* const* d_in, const int* in_sizes, int n_in,
                              void* d_out, int out_size)
{
    const float* x   = (const float*)d_in[0];
    const float* Wq  = (const float*)d_in[1];
    const float* Wk  = (const float*)d_in[2];
    const float* Wv  = (const float*)d_in[3];
    const float* Wo  = (const float*)d_in[4];
    const float* bo  = (const float*)d_in[5];
    const float* W1  = (const float*)d_in[6];
    const float* b1  = (const float*)d_in[7];
    const float* W2  = (const float*)d_in[8];
    const float* b2  = (const float*)d_in[9];
    const float* g1  = (const float*)d_in[10];
    const float* be1 = (const float*)d_in[11];
    const float* g2  = (const float*)d_in[12];
    const float* be2 = (const float*)d_in[13];
    float* out = (float*)d_out;

    half_t *xn, *qkv, *o, *xn2, *hb, *wqkv, *wo, *w1, *w2;
    float *x1;
    cudaGetSymbolAddress((void**)&xn,   g_xn);
    cudaGetSymbolAddress((void**)&qkv,  g_qkv);
    cudaGetSymbolAddress((void**)&o,    g_o);
    cudaGetSymbolAddress((void**)&x1,   g_x1);
    cudaGetSymbolAddress((void**)&xn2,  g_xn2);
    cudaGetSymbolAddress((void**)&hb,   g_h);
    cudaGetSymbolAddress((void**)&wqkv, g_wqkv);
    cudaGetSymbolAddress((void**)&wo,   g_wo);
    cudaGetSymbolAddress((void**)&w1,   g_w1);
    cudaGetSymbolAddress((void**)&w2,   g_w2);

    cudaFuncSetAttribute(mma_gemm_kernel<0>,
                         cudaFuncAttributeMaxDynamicSharedMemorySize, SMG_TOTAL);
    cudaFuncSetAttribute(mma_gemm_kernel<1>,
                         cudaFuncAttributeMaxDynamicSharedMemorySize, SMG_TOTAL);
    cudaFuncSetAttribute(mma_gemm_kernel<2>,
                         cudaFuncAttributeMaxDynamicSharedMemorySize, SMG_TOTAL);

    // all weight packing in one launch
    pack_all_kernel<<<(NW_TOT + 255) / 256, 256>>>(Wq, Wk, Wv, Wo, W1, W2,
                                                   wqkv, wo, w1, w2);

    // LN1
    ln_kernel<<<NROWS, 128>>>(x, g1, be1, xn);

    // QKV projection -> fp16
    mma_gemm_kernel<0><<<dim3(QKVW / 128, NROWS / 128), 128, SMG_TOTAL>>>(
        xn, wqkv, nullptr, qkv, CC, QKVW, nullptr, nullptr);

    // causal attention (tensor cores, double-buffered K/V)
    attn_kernel<<<dim3(4, HH, BB), 128>>>(qkv, o);

    // output projection + bias + residual -> f32
    mma_gemm_kernel<1><<<dim3(CC / 128, NROWS / 128), 128, SMG_TOTAL>>>(
        o, wo, x1, nullptr, CC, CC, bo, x);

    // LN2
    ln_kernel<<<NROWS, 128>>>(x1, g2, be2, xn2);

    // MLP up + ReLU -> fp16
    mma_gemm_kernel<2><<<dim3(FFN / 128, NROWS / 128), 128, SMG_TOTAL>>>(
        xn2, w1, nullptr, hb, CC, FFN, b1, nullptr);

    // MLP down + bias + residual -> out (f32)
    mma_gemm_kernel<1><<<dim3(CC / 128, NROWS / 128), 128, SMG_TOTAL>>>(
        hb, w2, out, nullptr, FFN, CC, b2, x1);
}

// round 9
// speedup vs baseline: 1.1550x; 1.1550x over previous
#include <cuda_runtime.h>
#include <cuda_fp16.h>
#include <math.h>
#include <stdint.h>

// Problem constants
#define BB   128
#define TT   256
#define CC   384
#define HH   6
#define DD   64
#define NROWS (BB*TT)          // 32768
#define QKVW  (3*CC)           // 1152
#define FFN   (4*CC)           // 1536
#define LN_EPS 1e-5f
#define ATT_SCALE 0.05103103630798287f   // 384^-0.5

typedef __half half_t;

// ---------------------------------------------------------------------------
// Scratch (device globals; allocation is forbidden)
// ---------------------------------------------------------------------------
__device__ half_t g_xn  [(size_t)NROWS*CC];
__device__ half_t g_qkv [(size_t)NROWS*QKVW];
__device__ half_t g_o   [(size_t)NROWS*CC];
__device__ float  g_x1  [(size_t)NROWS*CC];
__device__ half_t g_xn2 [(size_t)NROWS*CC];
__device__ half_t g_h   [(size_t)NROWS*FFN];
// packed weights, [N, K] K-major fp16
__device__ half_t g_wqkv[(size_t)QKVW*CC];
__device__ half_t g_wo  [(size_t)CC*CC];
__device__ half_t g_w1  [(size_t)FFN*CC];
__device__ half_t g_w2  [(size_t)CC*FFN];

// ---------------------------------------------------------------------------
// Helpers
// ---------------------------------------------------------------------------
__device__ __forceinline__ uint32_t smem_u32(const void* p) {
    return (uint32_t)__cvta_generic_to_shared(p);
}

#define CP_ASYNC16(dst, src) \
    asm volatile("cp.async.cg.shared.global [%0], [%1], 16;" :: "r"(dst), "l"(src))
#define CP_COMMIT() asm volatile("cp.async.commit_group;" ::: "memory")
#define CP_WAIT(n)  asm volatile("cp.async.wait_group %0;" :: "n"(n) : "memory")

#define LDSM_X4(r0, r1, r2, r3, addr) \
    asm volatile("ldmatrix.sync.aligned.m8n8.x4.shared.b16 {%0,%1,%2,%3}, [%4];" \
        : "=r"(r0), "=r"(r1), "=r"(r2), "=r"(r3) : "r"(addr))

#define LDSM_X4_T(r0, r1, r2, r3, addr) \
    asm volatile("ldmatrix.sync.aligned.m8n8.x4.trans.shared.b16 {%0,%1,%2,%3}, [%4];" \
        : "=r"(r0), "=r"(r1), "=r"(r2), "=r"(r3) : "r"(addr))

#define MMA_F16(d0, d1, d2, d3, a0, a1, a2, a3, b0, b1) \
    asm volatile("mma.sync.aligned.m16n8k16.row.col.f32.f16.f16.f32 " \
        "{%0,%1,%2,%3}, {%4,%5,%6,%7}, {%8,%9}, {%0,%1,%2,%3};" \
        : "+f"(d0), "+f"(d1), "+f"(d2), "+f"(d3) \
        : "r"(a0), "r"(a1), "r"(a2), "r"(a3), "r"(b0), "r"(b1))

__device__ __forceinline__ uint32_t pack_h2(float a, float b) {
    __half2 h = __floats2half2_rn(a, b);
    return *(uint32_t*)&h;
}

// ---------------------------------------------------------------------------
// Fused prep: LN (warp-per-row, float4 loads) + weight packing, one launch.
//   blocks [0, LN_BLOCKS)            : LayerNorm of x -> xn (fp16)
//   blocks [LN_BLOCKS, +PACK_BLOCKS) : pack/transpose all weights to fp16
// ---------------------------------------------------------------------------
#define NW_QKV (QKVW*CC)
#define NW_O   (CC*CC)
#define NW_1   (FFN*CC)
#define NW_2   (CC*FFN)
#define NW_TOT (NW_QKV+NW_O+NW_1+NW_2)
#define LN_BLOCKS   (NROWS/8)                  // 4096
#define PACK_BLOCKS ((NW_TOT + 255)/256)       // 6912

__device__ __forceinline__ void ln_row(const float* __restrict__ x,
                                       const float* __restrict__ g,
                                       const float* __restrict__ be,
                                       half_t* __restrict__ out,
                                       int row, int lane)
{
    const float4* xr = (const float4*)(x + (size_t)row * CC);
    float4 a = xr[lane], b4 = xr[lane + 32], c4 = xr[lane + 64];

    float s  = a.x + a.y + a.z + a.w + b4.x + b4.y + b4.z + b4.w
             + c4.x + c4.y + c4.z + c4.w;
    float sq = a.x*a.x + a.y*a.y + a.z*a.z + a.w*a.w
             + b4.x*b4.x + b4.y*b4.y + b4.z*b4.z + b4.w*b4.w
             + c4.x*c4.x + c4.y*c4.y + c4.z*c4.z + c4.w*c4.w;

    #pragma unroll
    for (int off = 16; off > 0; off >>= 1) {
        s  += __shfl_xor_sync(0xffffffffu, s,  off);
        sq += __shfl_xor_sync(0xffffffffu, sq, off);
    }
    const float mu  = s * (1.0f / CC);
    const float var = sq * (1.0f / CC) - mu * mu;
    const float inv = rsqrtf(var + LN_EPS);

    const float4* gv = (const float4*)g;
    const float4* bv = (const float4*)be;
    half_t* orow = out + (size_t)row * CC;

    #pragma unroll
    for (int p = 0; p < 3; p++) {
        int i4 = lane + p * 32;
        float4 v  = (p == 0) ? a : ((p == 1) ? b4 : c4);
        float4 gg = gv[i4];
        float4 bb = bv[i4];
        float y0 = (v.x - mu) * inv * gg.x + bb.x;
        float y1 = (v.y - mu) * inv * gg.y + bb.y;
        float y2 = (v.z - mu) * inv * gg.z + bb.z;
        float y3 = (v.w - mu) * inv * gg.w + bb.w;
        *(__half2*)&orow[i4 * 4]     = __floats2half2_rn(y0, y1);
        *(__half2*)&orow[i4 * 4 + 2] = __floats2half2_rn(y2, y3);
    }
}

__global__ void __launch_bounds__(256) prep_kernel(
    const float* __restrict__ x,
    const float* __restrict__ g1, const float* __restrict__ be1,
    half_t* __restrict__ xn,
    const float* __restrict__ Wq, const float* __restrict__ Wk,
    const float* __restrict__ Wv, const float* __restrict__ Wo,
    const float* __restrict__ W1, const float* __restrict__ W2,
    half_t* __restrict__ wqkv, half_t* __restrict__ wo,
    half_t* __restrict__ w1, half_t* __restrict__ w2)
{
    if (blockIdx.x < LN_BLOCKS) {
        const int warp = threadIdx.x >> 5, lane = threadIdx.x & 31;
        ln_row(x, g1, be1, xn, blockIdx.x * 8 + warp, lane);
        return;
    }
    int idx = (blockIdx.x - LN_BLOCKS) * 256 + threadIdx.x;
    if (idx < NW_QKV) {
        int n = idx / CC, k = idx % CC;
        int proj = n / CC, hd = n % CC;
        int h = hd >> 6, d = hd & 63;
        const float* W = (proj == 0) ? Wq : ((proj == 1) ? Wk : Wv);
        wqkv[idx] = __float2half(W[(size_t)(h * CC + k) * DD + d]);
        return;
    }
    idx -= NW_QKV;
    if (idx < NW_O) {
        int n = idx / CC, k = idx % CC;
        wo[idx] = __float2half(Wo[(size_t)k * CC + n]);
        return;
    }
    idx -= NW_O;
    if (idx < NW_1) {
        int n = idx / CC, k = idx % CC;
        w1[idx] = __float2half(W1[(size_t)k * FFN + n]);
        return;
    }
    idx -= NW_1;
    if (idx < NW_2) {
        int n = idx / FFN, k = idx % FFN;
        w2[idx] = __float2half(W2[(size_t)k * CC + n]);
    }
}

// standalone LN launch (for LN2)
__global__ void __launch_bounds__(256) ln_kernel(const float* __restrict__ x,
                                                 const float* __restrict__ g,
                                                 const float* __restrict__ be,
                                                 half_t* __restrict__ out)
{
    const int warp = threadIdx.x >> 5, lane = threadIdx.x & 31;
    ln_row(x, g, be, out, blockIdx.x * 8 + warp, lane);
}

// ---------------------------------------------------------------------------
// fp16 HMMA GEMM, 3-stage cp.async pipeline (R6 config: 8 warps, 64x32 tiles).
//   EPI 0: fp16 out   EPI 1: +bias+res -> f32   EPI 2: relu(+bias) -> fp16
// ---------------------------------------------------------------------------
#define RPAD 144
#define T_A  0
#define T_B  (128*RPAD)
#define BUFSZ (2*128*RPAD)            // 36864 per stage
#define NSTAGE 3
#define SMG_TOTAL (NSTAGE*BUFSZ)      // 110592

__device__ __forceinline__ void prefetch_chunk(
    uint32_t sbuf, const half_t* __restrict__ A, const half_t* __restrict__ B,
    int row0, int col0, int K, int k0, int tid)
{
    #pragma unroll
    for (int i = 0; i < 8; i++) {
        int idx = tid + i * 256;
        int r = idx >> 3, cp = idx & 7;
        if (r < 128) {
            CP_ASYNC16(sbuf + T_A + (uint32_t)(r * RPAD + cp * 16),
                       A + (size_t)(row0 + r) * K + k0 + cp * 8);
        } else {
            int rr = r - 128;
            CP_ASYNC16(sbuf + T_B + (uint32_t)(rr * RPAD + cp * 16),
                       B + (size_t)(col0 + rr) * K + k0 + cp * 8);
        }
    }
}

template <int EPI>
__global__ void __launch_bounds__(256)
mma_gemm_kernel(const half_t* __restrict__ A, const half_t* __restrict__ B,
                float* __restrict__ Cf, half_t* __restrict__ Ch,
                int K, int M,
                const float* __restrict__ bias, const float* __restrict__ res)
{
    extern __shared__ char sm[];
    const uint32_t sbase = smem_u32(sm);
    const int tid  = threadIdx.x;
    const int warp = tid >> 5, lane = tid & 31;
    const int wrow = warp >> 2, wcol = warp & 3;
    const int row0 = blockIdx.y * 128;
    const int col0 = blockIdx.x * 128;

    const int quad = lane >> 3, il = lane & 7;
    const uint32_t aoff = (uint32_t)((wrow * 64 + (quad & 1) * 8 + il) * RPAD
                                     + (quad >> 1) * 16);
    const uint32_t boff = (uint32_t)((wcol * 32 + (quad >> 1) * 8 + il) * RPAD
                                     + (quad & 1) * 16);

    float acc[4][4][4];
    #pragma unroll
    for (int m = 0; m < 4; m++)
        #pragma unroll
        for (int n = 0; n < 4; n++)
            #pragma unroll
            for (int k = 0; k < 4; k++) acc[m][n][k] = 0.0f;

    const int nch = K >> 6;

    prefetch_chunk(sbase, A, B, row0, col0, K, 0, tid);
    CP_COMMIT();
    prefetch_chunk(sbase + BUFSZ, A, B, row0, col0, K, 64, tid);
    CP_COMMIT();

    int sread = 0, swrite = 2;
    for (int ch = 0; ch < nch; ch++) {
        if (ch + 1 < nch) { CP_WAIT(1); } else { CP_WAIT(0); }
        __syncthreads();

        if (ch + 2 < nch) {
            prefetch_chunk(sbase + swrite * BUFSZ, A, B,
                           row0, col0, K, (ch + 2) << 6, tid);
            CP_COMMIT();
            swrite = (swrite + 1 == NSTAGE) ? 0 : swrite + 1;
        }

        const uint32_t sbuf = sbase + sread * BUFSZ;
        sread = (sread + 1 == NSTAGE) ? 0 : sread + 1;

        #pragma unroll
        for (int ks = 0; ks < 4; ks++) {
            const uint32_t ksb = ks * 32;
            uint32_t b[8];
            LDSM_X4(b[0], b[1], b[2], b[3], sbuf + T_B + boff + ksb);
            LDSM_X4(b[4], b[5], b[6], b[7], sbuf + T_B + boff + ksb + 16 * RPAD);

            #pragma unroll
            for (int mt = 0; mt < 4; mt++) {
                uint32_t a[4];
                LDSM_X4(a[0], a[1], a[2], a[3],
                        sbuf + T_A + aoff + mt * 16 * RPAD + ksb);
                #pragma unroll
                for (int nt = 0; nt < 4; nt++) {
                    float* d = acc[mt][nt];
                    MMA_F16(d[0], d[1], d[2], d[3],
                            a[0], a[1], a[2], a[3], b[nt*2], b[nt*2+1]);
                }
            }
        }
    }

    const int r_l = lane >> 2;
    const int c_l = (lane & 3) << 1;
    #pragma unroll
    for (int mt = 0; mt < 4; mt++) {
        #pragma unroll
        for (int nt = 0; nt < 4; nt++) {
            const int r = row0 + wrow * 64 + mt * 16 + r_l;
            const int c = col0 + wcol * 32 + nt * 8 + c_l;
            const float* d = acc[mt][nt];
            #pragma unroll
            for (int half_i = 0; half_i < 2; half_i++) {
                const int rr = r + half_i * 8;
                const size_t off = (size_t)rr * M + c;
                float v0 = d[half_i * 2], v1 = d[half_i * 2 + 1];
                if (EPI == 0) {
                    *(__half2*)&Ch[off] = __floats2half2_rn(v0, v1);
                } else if (EPI == 1) {
                    float2 rv = *(const float2*)&res[off];
                    *(float2*)&Cf[off] = make_float2(v0 + bias[c] + rv.x,
                                                     v1 + bias[c + 1] + rv.y);
                } else {
                    v0 = fmaxf(v0 + bias[c],     0.0f);
                    v1 = fmaxf(v1 + bias[c + 1], 0.0f);
                    *(__half2*)&Ch[off] = __floats2half2_rn(v0, v1);
                }
            }
        }
    }
}

// ---------------------------------------------------------------------------
// Tensor-core causal flash attention, q-tile 128 (8 warps), double-buffered
// 64-key K/V tiles. Each K/V tile now serves 128 q-rows (2x reuse vs R6).
// ---------------------------------------------------------------------------
#define ATPAD 144
#define AT_KV0 (128*ATPAD)
#define AT_KVSZ (2*64*ATPAD)
__global__ void __launch_bounds__(256) attn_kernel(const half_t* __restrict__ qkv,
                                                   half_t* __restrict__ o)
{
    __shared__ char smem[128 * ATPAD + 2 * AT_KVSZ];   // 55296 B
    const uint32_t sb  = smem_u32(smem);
    const uint32_t KV0 = sb + AT_KV0;

    const int qt = blockIdx.x;           // 0..1  (128-row q tiles)
    const int h  = blockIdx.y;
    const int b  = blockIdx.z;
    const int tid  = threadIdx.x;
    const int warp = tid >> 5, lane = tid & 31;
    const int quad = lane >> 3, il = lane & 7;
    const int r_l  = lane >> 2, c_l = (lane & 3) << 1;

    const size_t qrow0 = (size_t)(b * TT + qt * 128);
    const half_t* qg  = qkv + qrow0 * QKVW + h * 64;
    const half_t* kvg = qkv + (size_t)(b * TT) * QKVW + CC + h * 64;

    // stage Q (128x64 fp16): 1024 cp16 / 256 thr
    #pragma unroll
    for (int i = 0; i < 4; i++) {
        int idx = tid + i * 256;
        int r = idx >> 3, cp = idx & 7;
        CP_ASYNC16(sb + (uint32_t)(r * ATPAD + cp * 16),
                   qg + (size_t)r * QKVW + cp * 8);
    }
    CP_COMMIT();

    // prefetch K/V tile 0 into stage 0: 512+512 cp16 / 256 thr
    #pragma unroll
    for (int i = 0; i < 2; i++) {
        int idx = tid + i * 256;
        int r = idx >> 3, cp = idx & 7;
        const half_t* kg = kvg + (size_t)r * QKVW + cp * 8;
        CP_ASYNC16(KV0 + (uint32_t)(r * ATPAD + cp * 16), kg);
        CP_ASYNC16(KV0 + (uint32_t)((64 + r) * ATPAD + cp * 16), kg + CC);
    }
    CP_COMMIT();

    CP_WAIT(1);      // Q resident
    __syncthreads();

    // Q A-fragments for this warp's 16 rows
    uint32_t qa[4][4];
    {
        const uint32_t aoff = sb + (uint32_t)((warp * 16 + (quad & 1) * 8 + il) * ATPAD
                                              + (quad >> 1) * 16);
        #pragma unroll
        for (int ks = 0; ks < 4; ks++)
            LDSM_X4(qa[ks][0], qa[ks][1], qa[ks][2], qa[ks][3], aoff + ks * 32);
    }

    float m0 = -1e30f, m1 = -1e30f, l0 = 0.0f, l1 = 0.0f;
    float oacc[8][4];
    #pragma unroll
    for (int nt = 0; nt < 8; nt++)
        #pragma unroll
        for (int j = 0; j < 4; j++) oacc[nt][j] = 0.0f;

    const uint32_t klane = (uint32_t)(((quad >> 1) * 8 + il) * ATPAD + (quad & 1) * 16);
    const uint32_t vlane = (uint32_t)(((quad & 1) * 8 + il) * ATPAD + (quad >> 1) * 16);

    const int qrl0 = qt * 128 + warp * 16 + r_l;   // q row within sequence
    const int qrl1 = qrl0 + 8;
    const int njt  = 2 * qt + 2;

    for (int jt = 0; jt < njt; jt++) {
        CP_WAIT(0);
        __syncthreads();

        if (jt + 1 < njt) {
            const uint32_t kvn = KV0 + ((jt + 1) & 1) * AT_KVSZ;
            const half_t* kg0 = kvg + (size_t)((jt + 1) * 64) * QKVW;
            #pragma unroll
            for (int i = 0; i < 2; i++) {
                int idx = tid + i * 256;
                int r = idx >> 3, cp = idx & 7;
                const half_t* kg = kg0 + (size_t)r * QKVW + cp * 8;
                CP_ASYNC16(kvn + (uint32_t)(r * ATPAD + cp * 16), kg);
                CP_ASYNC16(kvn + (uint32_t)((64 + r) * ATPAD + cp * 16), kg + CC);
            }
            CP_COMMIT();
        }

        const uint32_t kvs = KV0 + (jt & 1) * AT_KVSZ;
        const uint32_t koff = kvs + klane;
        const uint32_t voff = kvs + 64 * ATPAD + vlane;

        // S = Q K^T
        float s[8][4];
        #pragma unroll
        for (int nt = 0; nt < 8; nt++)
            #pragma unroll
            for (int j = 0; j < 4; j++) s[nt][j] = 0.0f;

        #pragma unroll
        for (int np = 0; np < 4; np++) {
            #pragma unroll
            for (int ks = 0; ks < 4; ks++) {
                uint32_t bb[4];
                LDSM_X4(bb[0], bb[1], bb[2], bb[3],
                        koff + np * 16 * ATPAD + ks * 32);
                MMA_F16(s[2*np][0],   s[2*np][1],   s[2*np][2],   s[2*np][3],
                        qa[ks][0], qa[ks][1], qa[ks][2], qa[ks][3], bb[0], bb[1]);
                MMA_F16(s[2*np+1][0], s[2*np+1][1], s[2*np+1][2], s[2*np+1][3],
                        qa[ks][0], qa[ks][1], qa[ks][2], qa[ks][3], bb[2], bb[3]);
            }
        }

        // scale + causal mask (key tiles overlapping the diagonal: jt >= 2*qt)
        if (jt >= 2 * qt) {
            #pragma unroll
            for (int nt = 0; nt < 8; nt++) {
                int kcol = jt * 64 + nt * 8 + c_l;
                s[nt][0] = (kcol     > qrl0) ? -1e30f : s[nt][0] * ATT_SCALE;
                s[nt][1] = (kcol + 1 > qrl0) ? -1e30f : s[nt][1] * ATT_SCALE;
                s[nt][2] = (kcol     > qrl1) ? -1e30f : s[nt][2] * ATT_SCALE;
                s[nt][3] = (kcol + 1 > qrl1) ? -1e30f : s[nt][3] * ATT_SCALE;
            }
        } else {
            #pragma unroll
            for (int nt = 0; nt < 8; nt++)
                #pragma unroll
                for (int j = 0; j < 4; j++) s[nt][j] *= ATT_SCALE;
        }

        // online softmax
        float mx0 = -1e30f, mx1 = -1e30f;
        #pragma unroll
        for (int nt = 0; nt < 8; nt++) {
            mx0 = fmaxf(mx0, fmaxf(s[nt][0], s[nt][1]));
            mx1 = fmaxf(mx1, fmaxf(s[nt][2], s[nt][3]));
        }
        mx0 = fmaxf(mx0, __shfl_xor_sync(0xffffffffu, mx0, 1));
        mx0 = fmaxf(mx0, __shfl_xor_sync(0xffffffffu, mx0, 2));
        mx1 = fmaxf(mx1, __shfl_xor_sync(0xffffffffu, mx1, 1));
        mx1 = fmaxf(mx1, __shfl_xor_sync(0xffffffffu, mx1, 2));

        const float nm0 = fmaxf(m0, mx0), nm1 = fmaxf(m1, mx1);
        const float fac0 = __expf(m0 - nm0), fac1 = __expf(m1 - nm1);
        m0 = nm0; m1 = nm1;

        float ps0 = 0.0f, ps1 = 0.0f;
        #pragma unroll
        for (int nt = 0; nt < 8; nt++) {
            s[nt][0] = __expf(s[nt][0] - nm0);
            s[nt][1] = __expf(s[nt][1] - nm0);
            s[nt][2] = __expf(s[nt][2] - nm1);
            s[nt][3] = __expf(s[nt][3] - nm1);
            ps0 += s[nt][0] + s[nt][1];
            ps1 += s[nt][2] + s[nt][3];
        }
        ps0 += __shfl_xor_sync(0xffffffffu, ps0, 1);
        ps0 += __shfl_xor_sync(0xffffffffu, ps0, 2);
        ps1 += __shfl_xor_sync(0xffffffffu, ps1, 1);
        ps1 += __shfl_xor_sync(0xffffffffu, ps1, 2);
        l0 = l0 * fac0 + ps0;
        l1 = l1 * fac1 + ps1;

        #pragma unroll
        for (int nt = 0; nt < 8; nt++) {
            oacc[nt][0] *= fac0; oacc[nt][1] *= fac0;
            oacc[nt][2] *= fac1; oacc[nt][3] *= fac1;
        }

        // O += P V
        #pragma unroll
        for (int ks = 0; ks < 4; ks++) {
            uint32_t pa[4];
            pa[0] = pack_h2(s[2*ks][0],   s[2*ks][1]);
            pa[1] = pack_h2(s[2*ks][2],   s[2*ks][3]);
            pa[2] = pack_h2(s[2*ks+1][0], s[2*ks+1][1]);
            pa[3] = pack_h2(s[2*ks+1][2], s[2*ks+1][3]);
            #pragma unroll
            for (int np = 0; np < 4; np++) {
                uint32_t vb[4];
                LDSM_X4_T(vb[0], vb[1], vb[2], vb[3],
                          voff + ks * 16 * ATPAD + np * 32);
                MMA_F16(oacc[2*np][0],   oacc[2*np][1],   oacc[2*np][2],   oacc[2*np][3],
                        pa[0], pa[1], pa[2], pa[3], vb[0], vb[1]);
                MMA_F16(oacc[2*np+1][0], oacc[2*np+1][1], oacc[2*np+1][2], oacc[2*np+1][3],
                        pa[0], pa[1], pa[2], pa[3], vb[2], vb[3]);
            }
        }
    }

    const float inv0 = 1.0f / l0, inv1 = 1.0f / l1;
    half_t* og = o + (qrow0 + warp * 16) * CC + h * 64;
    #pragma unroll
    for (int nt = 0; nt < 8; nt++) {
        const int col = nt * 8 + c_l;
        *(__half2*)&og[(size_t)r_l * CC + col] =
            __floats2half2_rn(oacc[nt][0] * inv0, oacc[nt][1] * inv0);
        *(__half2*)&og[(size_t)(r_l + 8) * CC + col] =
            __floats2half2_rn(oacc[nt][2] * inv1, oacc[nt][3] * inv1);
    }
}

// ---------------------------------------------------------------------------
// Launch
// ---------------------------------------------------------------------------
extern "C" void kernel_launch(void* const* d_in, const int* in_sizes, int n_in,
                              void* d_out, int out_size)
{
    const float* x   = (const float*)d_in[0];
    const float* Wq  = (const float*)d_in[1];
    const float* Wk  = (const float*)d_in[2];
    const float* Wv  = (const float*)d_in[3];
    const float* Wo  = (const float*)d_in[4];
    const float* bo  = (const float*)d_in[5];
    const float* W1  = (const float*)d_in[6];
    const float* b1  = (const float*)d_in[7];
    const float* W2  = (const float*)d_in[8];
    const float* b2  = (const float*)d_in[9];
    const float* g1  = (const float*)d_in[10];
    const float* be1 = (const float*)d_in[11];
    const float* g2  = (const float*)d_in[12];
    const float* be2 = (const float*)d_in[13];
    float* out = (float*)d_out;

    half_t *xn, *qkv, *o, *xn2, *hb, *wqkv, *wo, *w1, *w2;
    float *x1;
    cudaGetSymbolAddress((void**)&xn,   g_xn);
    cudaGetSymbolAddress((void**)&qkv,  g_qkv);
    cudaGetSymbolAddress((void**)&o,    g_o);
    cudaGetSymbolAddress((void**)&x1,   g_x1);
    cudaGetSymbolAddress((void**)&xn2,  g_xn2);
    cudaGetSymbolAddress((void**)&hb,   g_h);
    cudaGetSymbolAddress((void**)&wqkv, g_wqkv);
    cudaGetSymbolAddress((void**)&wo,   g_wo);
    cudaGetSymbolAddress((void**)&w1,   g_w1);
    cudaGetSymbolAddress((void**)&w2,   g_w2);

    cudaFuncSetAttribute(mma_gemm_kernel<0>,
                         cudaFuncAttributeMaxDynamicSharedMemorySize, SMG_TOTAL);
    cudaFuncSetAttribute(mma_gemm_kernel<1>,
                         cudaFuncAttributeMaxDynamicSharedMemorySize, SMG_TOTAL);
    cudaFuncSetAttribute(mma_gemm_kernel<2>,
                         cudaFuncAttributeMaxDynamicSharedMemorySize, SMG_TOTAL);

    // fused LN1 + weight packing
    prep_kernel<<<LN_BLOCKS + PACK_BLOCKS, 256>>>(
        x, g1, be1, xn, Wq, Wk, Wv, Wo, W1, W2, wqkv, wo, w1, w2);

    // QKV projection -> fp16
    mma_gemm_kernel<0><<<dim3(QKVW / 128, NROWS / 128), 256, SMG_TOTAL>>>(
        xn, wqkv, nullptr, qkv, CC, QKVW, nullptr, nullptr);

    // causal attention (tensor cores, 128-row q tiles)
    attn_kernel<<<dim3(2, HH, BB), 256>>>(qkv, o);

    // output projection + bias + residual -> f32
    mma_gemm_kernel<1><<<dim3(CC / 128, NROWS / 128), 256, SMG_TOTAL>>>(
        o, wo, x1, nullptr, CC, CC, bo, x);

    // LN2
    ln_kernel<<<NROWS / 8, 256>>>(x1, g2, be2, xn2);

    // MLP up + ReLU -> fp16
    mma_gemm_kernel<2><<<dim3(FFN / 128, NROWS / 128), 256, SMG_TOTAL>>>(
        xn2, w1, nullptr, hb, CC, FFN, b1, nullptr);

    // MLP down + bias + residual -> out (f32)
    mma_gemm_kernel<1><<<dim3(CC / 128, NROWS / 128), 256, SMG_TOTAL>>>(
        hb, w2, out, nullptr, FFN, CC, b2, x1);
}